// round 17
// baseline (speedup 1.0000x reference)
#include <cuda_runtime.h>
#include <cuda_fp16.h>
#include <cstdint>

// ---------------------------------------------------------------------------
// Problem constants
// ---------------------------------------------------------------------------
static constexpr int NPAPER  = 200000;
static constexpr int NAUTHOR = 100000;
static constexpr int HID     = 128;     // 4 heads x 32 channels
static constexpr int ECITES  = 1000000;
static constexpr int EWRITES = 500000;
static constexpr int EWB     = 500000;
static constexpr int ETOT    = ECITES + EWRITES + EWB;   // 2,000,000
static constexpr int NTOT    = 2 * NPAPER + NAUTHOR;     // 500,000

static constexpr size_t SZ_P = (size_t)NPAPER * HID;
static constexpr size_t SZ_A = (size_t)NAUTHOR * HID;

// float scratch: logits + fp32 V + folded layer-0 biases
static constexpr size_t O_LP1  = 0;
static constexpr size_t O_LP2  = O_LP1 + (size_t)NPAPER * 16;
static constexpr size_t O_LA   = O_LP2 + (size_t)NPAPER * 16;
static constexpr size_t O_VF   = O_LA  + (size_t)NAUTHOR * 16;   // 5 x [128][16] fp32
static constexpr size_t O_BB   = O_VF + 5 * 2048;                // [384] folded L0 biases
static constexpr size_t SCRATCH_FLOATS = O_BB + 384;

__device__ float g_scratch[SCRATCH_FLOATS];

// half scratch
static constexpr size_t H_XPA  = 0;                 // layer-1 paper out / classifier in
static constexpr size_t H_XPB  = H_XPA + SZ_P;      // layer-0 paper out
static constexpr size_t H_XAB  = H_XPB + SZ_P;      // layer-0 author out
static constexpr size_t H_HP0  = H_XAB + SZ_A;
static constexpr size_t H_HP2  = H_HP0 + SZ_P;
static constexpr size_t H_HA1  = H_HP2 + SZ_P;
static constexpr size_t H_W1   = H_HA1 + SZ_A;      // 3 x [128,128] fp16 (layer-1)
static constexpr size_t H_WLIN = H_W1 + 49152;      // [128,64]
static constexpr size_t H_CWP0 = H_WLIN + 8192;     // Wp@W0[0]  [256,128]
static constexpr size_t H_CWP2 = H_CWP0 + 32768;    // Wp@W0[2]  [256,128]
static constexpr size_t H_CWA  = H_CWP2 + 32768;    // Wa@W0[1]  [128,128]
static constexpr size_t H_CV0  = H_CWA + 16384;     // Wp@V_m0   [256,16]
static constexpr size_t H_CV2  = H_CV0 + 4096;      // Wp@V_m2   [256,16]
static constexpr size_t H_CVA  = H_CV2 + 4096;      // Wa@V_m3   [128,16]
static constexpr size_t H_V16  = H_CVA + 2048;      // V m1, m4 fp16 (layer-1)
static constexpr size_t SCRATCH_HALF = H_V16 + 2 * 2048;

__device__ __half g_hscratch[SCRATCH_HALF];

// int scratch: merged CSR
static constexpr size_t I_DEGS = 0;
static constexpr size_t I_OFFS = I_DEGS + NTOT;
static constexpr size_t I_CURS = I_OFFS + NTOT;
static constexpr size_t I_SRCS = I_CURS + NTOT;
static constexpr size_t SCRATCH_INTS = I_SRCS + ETOT;

__device__ int g_iscratch[SCRATCH_INTS];
__device__ unsigned long long g_flags[256];   // lookback-scan state

// ---------------------------------------------------------------------------
// fp16 mma + ldmatrix + cp.async helpers (sm_80+ PTX)
// ---------------------------------------------------------------------------
__device__ __forceinline__ void mma_f16(float* c, uint32_t a0, uint32_t a1,
                                        uint32_t a2, uint32_t a3,
                                        uint32_t b0, uint32_t b1) {
    asm volatile(
        "mma.sync.aligned.m16n8k16.row.col.f32.f16.f16.f32 "
        "{%0,%1,%2,%3}, {%4,%5,%6,%7}, {%8,%9}, {%0,%1,%2,%3};"
        : "+f"(c[0]), "+f"(c[1]), "+f"(c[2]), "+f"(c[3])
        : "r"(a0), "r"(a1), "r"(a2), "r"(a3), "r"(b0), "r"(b1));
}

__device__ __forceinline__ void ldm_x4(uint32_t* r, uint32_t addr) {
    asm volatile("ldmatrix.sync.aligned.m8n8.x4.shared.b16 {%0,%1,%2,%3}, [%4];"
                 : "=r"(r[0]), "=r"(r[1]), "=r"(r[2]), "=r"(r[3]) : "r"(addr));
}
__device__ __forceinline__ void ldm_x4t(uint32_t* r, uint32_t addr) {
    asm volatile("ldmatrix.sync.aligned.m8n8.x4.trans.shared.b16 {%0,%1,%2,%3}, [%4];"
                 : "=r"(r[0]), "=r"(r[1]), "=r"(r[2]), "=r"(r[3]) : "r"(addr));
}
__device__ __forceinline__ void ldm_x2t(uint32_t* r, uint32_t addr) {
    asm volatile("ldmatrix.sync.aligned.m8n8.x2.trans.shared.b16 {%0,%1}, [%2];"
                 : "=r"(r[0]), "=r"(r[1]) : "r"(addr));
}

__device__ __forceinline__ void cp16_zfill(uint32_t daddr, const void* g, int sz) {
    asm volatile("cp.async.cg.shared.global [%0], [%1], 16, %2;"
                 :: "r"(daddr), "l"(g), "r"(sz));
}
__device__ __forceinline__ void cp16(uint32_t daddr, const void* g) {
    asm volatile("cp.async.ca.shared.global [%0], [%1], 16;"
                 :: "r"(daddr), "l"(g));
}
__device__ __forceinline__ void cp_wait_all() {
    asm volatile("cp.async.commit_group;");
    asm volatile("cp.async.wait_group 0;");
}

// ---------------------------------------------------------------------------
// Prep 1: V matrices = W @ att (per head), fp32. 5 x [128][16] (see R7/R14).
// ---------------------------------------------------------------------------
__global__ void prep_v_k(const float* __restrict__ W0, const float* __restrict__ as0,
                         const float* __restrict__ ad0, const float* __restrict__ W1,
                         const float* __restrict__ as1, const float* __restrict__ ad1,
                         float* __restrict__ V) {
    int idx = blockIdx.x * blockDim.x + threadIdx.x;
    if (idx >= 5 * 2048) return;
    int m = idx >> 11;
    int r = idx & 2047;
    int k = r >> 4;
    int j = r & 15;
    int h = j & 3;
    int q = j >> 2;

    const float* Wm = nullptr;
    const float* at = nullptr;
    if (m == 0 || m == 1) {
        const float* W  = m ? W1 : W0;
        const float* as_ = m ? as1 : as0;
        const float* ad_ = m ? ad1 : ad0;
        if (q == 0)      { Wm = W;          at = as_; }
        else if (q == 1) { Wm = W;          at = ad_; }
        else if (q == 2) { Wm = W + 16384;  at = ad_ + 128; }
    } else if (m == 2) {
        if (q == 0) { Wm = W0 + 2 * 16384; at = as0 + 256; }
    } else if (m == 3) {
        if (q == 0)      { Wm = W0 + 16384;     at = as0 + 128; }
        else if (q == 1) { Wm = W0 + 2 * 16384; at = ad0 + 256; }
    } else {
        if (q == 0) { Wm = W1 + 16384; at = as1 + 128; }
    }
    float v = 0.f;
    if (Wm) {
#pragma unroll
        for (int c = 0; c < 32; c++)
            v += Wm[k * 128 + h * 32 + c] * at[h * 32 + c];
    }
    V[m * 2048 + k * 16 + j] = v;
}

// ---------------------------------------------------------------------------
// Prep 2: combined layer-0 operators + fp16 conversion of W1/Wlin (merged).
// ---------------------------------------------------------------------------
__global__ void prep_cw_k(const float* __restrict__ Wp, const float* __restrict__ Wa,
                          const float* __restrict__ W0, const float* __restrict__ bp,
                          const float* __restrict__ ba, const float* __restrict__ b0,
                          const float* __restrict__ Vf,
                          const float* __restrict__ W1, const float* __restrict__ Wlin,
                          __half* __restrict__ CWP0, __half* __restrict__ CWP2,
                          __half* __restrict__ CWA,  __half* __restrict__ CV0,
                          __half* __restrict__ CV2,  __half* __restrict__ CVA,
                          __half* __restrict__ V16,  float* __restrict__ BB,
                          __half* __restrict__ HW1,  __half* __restrict__ HWL) {
    int idx = blockIdx.x * blockDim.x + threadIdx.x;
    if (idx >= 153984) return;
    if (idx < 32768) {
        int i = idx >> 7, n = idx & 127;
        float s = 0.f;
        for (int c = 0; c < 128; c++) s += Wp[i * 128 + c] * W0[c * 128 + n];
        CWP0[idx] = __float2half_rn(s);
    } else if (idx < 65536) {
        int r = idx - 32768, i = r >> 7, n = r & 127;
        float s = 0.f;
        for (int c = 0; c < 128; c++) s += Wp[i * 128 + c] * W0[2 * 16384 + c * 128 + n];
        CWP2[r] = __float2half_rn(s);
    } else if (idx < 81920) {
        int r = idx - 65536, i = r >> 7, n = r & 127;
        float s = 0.f;
        for (int c = 0; c < 128; c++) s += Wa[i * 128 + c] * W0[16384 + c * 128 + n];
        CWA[r] = __float2half_rn(s);
    } else if (idx < 86016) {
        int r = idx - 81920, i = r >> 4, j = r & 15;
        float s = 0.f;
        for (int c = 0; c < 128; c++) s += Wp[i * 128 + c] * Vf[c * 16 + j];
        CV0[r] = __float2half_rn(s);
    } else if (idx < 90112) {
        int r = idx - 86016, i = r >> 4, j = r & 15;
        float s = 0.f;
        for (int c = 0; c < 128; c++) s += Wp[i * 128 + c] * Vf[2 * 2048 + c * 16 + j];
        CV2[r] = __float2half_rn(s);
    } else if (idx < 92160) {
        int r = idx - 90112, i = r >> 4, j = r & 15;
        float s = 0.f;
        for (int c = 0; c < 128; c++) s += Wa[i * 128 + c] * Vf[3 * 2048 + c * 16 + j];
        CVA[r] = __float2half_rn(s);
    } else if (idx < 94208) {
        int r = idx - 92160;
        V16[r] = __float2half_rn(Vf[1 * 2048 + r]);
    } else if (idx < 96256) {
        int r = idx - 94208;
        V16[2048 + r] = __float2half_rn(Vf[4 * 2048 + r]);
    } else if (idx < 96640) {
        int r = idx - 96256;
        float s;
        if (r < 128) {
            s = b0[r];
            for (int c = 0; c < 128; c++) s += bp[c] * W0[c * 128 + r];
            BB[r] = s;
        } else if (r < 256) {
            int j = r - 128;
            s = b0[128 + j];
            for (int c = 0; c < 128; c++) s += ba[c] * W0[16384 + c * 128 + j];
            BB[r] = s;
        } else {
            int j = r - 256;
            s = b0[256 + j];
            for (int c = 0; c < 128; c++) s += bp[c] * W0[2 * 16384 + c * 128 + j];
            BB[r] = s;
        }
    } else if (idx < 145792) {           // HW1 (49152)
        int r = idx - 96640;
        HW1[r] = __float2half_rn(W1[r]);
    } else {                             // HWL (8192)
        int r = idx - 145792;
        HWL[r] = __float2half_rn(Wlin[r]);
    }
}

// ---------------------------------------------------------------------------
// fp16 mma.sync GEMM (m16n8k16 + ldmatrix + cp.async staging).
// DUAL: two B/C pairs share one staged A. PAIR: blocks >= gridA run a second
// independent problem. DUAL and PAIR mutually exclusive.
// ---------------------------------------------------------------------------
template <int N, int KCH, bool VEXT, bool HALF, bool AHALF, bool DUAL, bool PAIR>
__global__ void __launch_bounds__(256, 2)
mma_gemm(const void* __restrict__ Av_,
         const __half* __restrict__ W1p_, const __half* __restrict__ V1_,
         void* __restrict__ C1_, float* __restrict__ L1_,
         const __half* __restrict__ W2p, const __half* __restrict__ V2,
         void* __restrict__ C2, float* __restrict__ L2,
         const float* __restrict__ bias, int M_,
         const void* __restrict__ Avb, int Mb, int gridA) {
    constexpr int LDA_S = 136;
    constexpr int LDB_S = N + 8;
    constexpr int NF    = N / 16;
    constexpr int KTOT  = KCH * 128;
    constexpr int NC    = VEXT ? N - 16 : N;
    constexpr int ACH   = DUAL ? KCH : 1;

    extern __shared__ __half smh[];
    __half* As = smh;
    __half* Bs = smh + (size_t)ACH * 128 * LDA_S;

    const int tid  = threadIdx.x;
    const int wid  = tid >> 5;
    const int lane = tid & 31;
    const int wm   = wid >> 1;
    const int wn   = wid & 1;
    const int g    = lane >> 2;
    const int tg   = lane & 3;

    const void* Av = Av_;
    const __half* Wsel = W1p_;
    const __half* Vsel = V1_;
    void* Csel = C1_;
    float* Lsel = L1_;
    int M = M_;
    int row0;
    if (PAIR && blockIdx.x >= gridA) {
        Av = Avb; Wsel = W2p; Vsel = V2; Csel = C2; Lsel = L2; M = Mb;
        row0 = (blockIdx.x - gridA) * 128;
    } else {
        row0 = blockIdx.x * 128;
    }

    const uint32_t asBase = (uint32_t)__cvta_generic_to_shared(As);
    const uint32_t bsBase = (uint32_t)__cvta_generic_to_shared(Bs);
    const int lrow = (lane & 7) + ((lane >> 3) & 1) * 8;
    const int lcol = (lane >> 4) * 8;

    float acc[2][NF][4];

    for (int pass = 0; pass < (DUAL ? 2 : 1); pass++) {
        const __half* W  = pass ? W2p : Wsel;
        const __half* Vx = pass ? V2 : Vsel;
        void* Cv  = pass ? C2 : Csel;
        float* Lb = pass ? L2 : Lsel;

#pragma unroll
        for (int mf = 0; mf < 2; mf++)
#pragma unroll
            for (int nf = 0; nf < NF; nf++)
#pragma unroll
                for (int j = 0; j < 4; j++) acc[mf][nf][j] = 0.f;

        for (int kc = 0; kc < KCH; kc++) {
            const int k0g = kc * 128;
            const int aslot = DUAL ? kc : 0;
            __half* Asl = As + (size_t)aslot * 128 * LDA_S;
            const uint32_t asB = asBase + (uint32_t)(aslot * 128 * LDA_S * 2);

#pragma unroll
            for (int i = tid; i < 128 * (N / 8); i += 256) {
                int k = i / (N / 8), n8 = i % (N / 8);
                const void* gsrc;
                if (!VEXT || n8 < NC / 8)
                    gsrc = W + (size_t)(k0g + k) * NC + n8 * 8;
                else
                    gsrc = Vx + (size_t)((k0g + k) * 2 + (n8 - NC / 8)) * 8;
                cp16(bsBase + (uint32_t)(k * LDB_S + n8 * 8) * 2, gsrc);
            }
            if (pass == 0) {
                if (AHALF) {
                    const __half* A = (const __half*)Av;
#pragma unroll
                    for (int i = tid; i < 128 * 16; i += 256) {
                        int r = i >> 4, c8 = i & 15;
                        int gr = row0 + r;
                        const void* gsrc = A + (size_t)(gr < M ? gr : 0) * KTOT + k0g + c8 * 8;
                        cp16_zfill(asB + (uint32_t)(r * LDA_S + c8 * 8) * 2, gsrc,
                                   (gr < M) ? 16 : 0);
                    }
                } else {
                    const float* A = (const float*)Av;
#pragma unroll
                    for (int i = tid; i < 128 * 32; i += 256) {
                        int r = i >> 5, c4 = i & 31;
                        int gr = row0 + r;
                        float4 v = make_float4(0.f, 0.f, 0.f, 0.f);
                        if (gr < M)
                            v = *reinterpret_cast<const float4*>(A + (size_t)gr * KTOT + k0g + c4 * 4);
                        __half2* dst = reinterpret_cast<__half2*>(Asl + r * LDA_S + c4 * 4);
                        dst[0] = __floats2half2_rn(v.x, v.y);
                        dst[1] = __floats2half2_rn(v.z, v.w);
                    }
                }
            }
            cp_wait_all();
            __syncthreads();

#pragma unroll
            for (int s = 0; s < 8; s++) {
                const int kk = s * 16;
                uint32_t a[2][4];
#pragma unroll
                for (int mf = 0; mf < 2; mf++) {
                    int row = wm * 32 + mf * 16 + lrow;
                    ldm_x4(a[mf], asB + (uint32_t)(row * LDA_S + kk + lcol) * 2);
                }
                uint32_t b[NF][2];
#pragma unroll
                for (int nf2 = 0; nf2 < NF / 2; nf2++) {
                    int n0 = wn * (N / 2) + nf2 * 16;
                    uint32_t r4[4];
                    ldm_x4t(r4, bsBase + (uint32_t)((kk + lrow) * LDB_S + n0 + lcol) * 2);
                    b[nf2 * 2][0] = r4[0]; b[nf2 * 2][1] = r4[1];
                    b[nf2 * 2 + 1][0] = r4[2]; b[nf2 * 2 + 1][1] = r4[3];
                }
                if (NF & 1) {
                    int n0 = wn * (N / 2) + (NF - 1) * 8;
                    ldm_x2t(b[NF - 1], bsBase + (uint32_t)((kk + lrow) * LDB_S + n0) * 2);
                }
#pragma unroll
                for (int mf = 0; mf < 2; mf++)
#pragma unroll
                    for (int nf = 0; nf < NF; nf++)
                        mma_f16(acc[mf][nf], a[mf][0], a[mf][1], a[mf][2], a[mf][3],
                                b[nf][0], b[nf][1]);
            }
            __syncthreads();
        }

#pragma unroll
        for (int mf = 0; mf < 2; mf++) {
            const int r0 = row0 + wm * 32 + mf * 16 + g;
            const int r1 = r0 + 8;
#pragma unroll
            for (int nf = 0; nf < NF; nf++) {
                const int col = wn * (N / 2) + nf * 8 + tg * 2;
                float c0 = acc[mf][nf][0], c1 = acc[mf][nf][1];
                float c2 = acc[mf][nf][2], c3 = acc[mf][nf][3];
                if (!VEXT || col < NC) {
                    if (bias) {
                        float b0v = bias[col], b1v = bias[col + 1];
                        c0 += b0v; c1 += b1v; c2 += b0v; c3 += b1v;
                    }
                    if (HALF) {
                        __half* C = (__half*)Cv;
                        if (r0 < M)
                            *reinterpret_cast<__half2*>(C + (size_t)r0 * NC + col) =
                                __floats2half2_rn(c0, c1);
                        if (r1 < M)
                            *reinterpret_cast<__half2*>(C + (size_t)r1 * NC + col) =
                                __floats2half2_rn(c2, c3);
                    } else {
                        float* C = (float*)Cv;
                        if (r0 < M)
                            *reinterpret_cast<float2*>(C + (size_t)r0 * NC + col) = make_float2(c0, c1);
                        if (r1 < M)
                            *reinterpret_cast<float2*>(C + (size_t)r1 * NC + col) = make_float2(c2, c3);
                    }
                } else {
                    const int lc = col - NC;
                    if (r0 < M)
                        *reinterpret_cast<float2*>(Lb + (size_t)r0 * 16 + lc) = make_float2(c0, c1);
                    if (r1 < M)
                        *reinterpret_cast<float2*>(Lb + (size_t)r1 * 16 + lc) = make_float2(c2, c3);
                }
            }
        }
        if (DUAL && pass == 0) __syncthreads();
    }
}

// ---------------------------------------------------------------------------
// Merged CSR build: hist + single-kernel decoupled-lookback scan + scatter
// ---------------------------------------------------------------------------
__global__ void hist3_k(const int* __restrict__ dc, const int* __restrict__ dw,
                        const int* __restrict__ db, int* __restrict__ degs) {
    int e = blockIdx.x * blockDim.x + threadIdx.x;
    if (e >= ETOT) return;
    int slot;
    if (e < ECITES)                slot = dc[e];
    else if (e < ECITES + EWRITES) slot = NPAPER + dw[e - ECITES];
    else                           slot = 2 * NPAPER + db[e - ECITES - EWRITES];
    atomicAdd(&degs[slot], 1);
}

// One-kernel exclusive scan (decoupled lookback). flags pre-zeroed.
// state in bits[63:62]: 0=invalid, 1=aggregate, 2=inclusive-prefix.
__global__ void scan_k(const int* __restrict__ deg, int* __restrict__ off,
                       int* __restrict__ cur, int n) {
    __shared__ int sh[256];
    __shared__ int s_prefix;
    const int t = threadIdx.x, b = blockIdx.x;
    const int base = b * 2048 + t * 8;
    int v[8], s = 0;
#pragma unroll
    for (int i = 0; i < 8; i++) {
        int idx = base + i;
        v[i] = (idx < n) ? deg[idx] : 0;
        s += v[i];
    }
    sh[t] = s;
    __syncthreads();
    for (int o = 1; o < 256; o <<= 1) {
        int y = (t >= o) ? sh[t - o] : 0;
        __syncthreads();
        sh[t] += y;
        __syncthreads();
    }
    int run = sh[t] - s;   // exclusive prefix within block

    if (t == 255) {
        int total = sh[255];
        volatile unsigned long long* fl = g_flags;
        int pre = 0;
        if (b == 0) {
            fl[0] = (2ULL << 62) | (unsigned int)total;
        } else {
            fl[b] = (1ULL << 62) | (unsigned int)total;   // publish aggregate
            int p = b - 1;
            while (true) {
                unsigned long long f = fl[p];
                unsigned long long st = f >> 62;
                if (st == 0) continue;
                pre += (int)(unsigned int)(f & 0xFFFFFFFFULL);
                if (st == 2ULL) break;
                p--;
            }
            fl[b] = (2ULL << 62) | (unsigned int)(pre + total);
        }
        s_prefix = pre;
    }
    __syncthreads();
    run += s_prefix;
#pragma unroll
    for (int i = 0; i < 8; i++) {
        int idx = base + i;
        if (idx < n) { off[idx] = run; cur[idx] = run; }
        run += v[i];
    }
}

__global__ void scatter3_k(const int* __restrict__ sc, const int* __restrict__ dc,
                           const int* __restrict__ sw, const int* __restrict__ dw,
                           const int* __restrict__ sb, const int* __restrict__ db,
                           int* __restrict__ curs, int* __restrict__ srcs) {
    int e = blockIdx.x * blockDim.x + threadIdx.x;
    if (e >= ETOT) return;
    int slot, sv;
    if (e < ECITES)                { slot = dc[e]; sv = sc[e]; }
    else if (e < ECITES + EWRITES) { int i = e - ECITES; slot = NPAPER + dw[i]; sv = sw[i]; }
    else                           { int i = e - ECITES - EWRITES; slot = 2 * NPAPER + db[i]; sv = sb[i]; }
    srcs[atomicAdd(&curs[slot], 1)] = sv;
}

// ---------------------------------------------------------------------------
// Dst-major GAT aggregation: 2 nodes per warp, lane owns 8 channels (uint4).
// Paper nodes: both relations interleaved -> 4 gathers in flight.
// ---------------------------------------------------------------------------
__device__ __forceinline__ float lrelu02(float v) { return v > 0.f ? v : 0.2f * v; }

struct F8 { float v[8]; };

__device__ __forceinline__ F8 gather_h8(const __half* __restrict__ hbuf,
                                        int sidx, int l16) {
    uint4 u = reinterpret_cast<const uint4*>(hbuf + (size_t)sidx * HID)[l16];
    F8 r;
    const uint32_t* p = &u.x;
#pragma unroll
    for (int i = 0; i < 4; i++) {
        __half2 h2 = *reinterpret_cast<const __half2*>(&p[i]);
        float2 f = __half22float2(h2);
        r.v[2 * i] = f.x;
        r.v[2 * i + 1] = f.y;
    }
    return r;
}

__device__ __forceinline__ void agg_rel(const int* __restrict__ srcs, int st, int d,
                                        const float* __restrict__ Lsrc, float ad,
                                        const __half* __restrict__ hbuf,
                                        int l16, int h, float* a, float& s) {
    int j = 0;
    for (; j + 2 <= d; j += 2) {
        int s0 = srcs[st + j];
        int s1 = srcs[st + j + 1];
        float l0 = Lsrc[(size_t)s0 * 16 + h];
        float l1 = Lsrc[(size_t)s1 * 16 + h];
        F8 h0 = gather_h8(hbuf, s0, l16);
        F8 h1 = gather_h8(hbuf, s1, l16);
        float x0 = __expf(lrelu02(l0 + ad));
        float x1 = __expf(lrelu02(l1 + ad));
        s += x0 + x1;
#pragma unroll
        for (int i = 0; i < 8; i++) a[i] += x0 * h0.v[i] + x1 * h1.v[i];
    }
    if (j < d) {
        int s0 = srcs[st + j];
        float x0 = __expf(lrelu02(Lsrc[(size_t)s0 * 16 + h] + ad));
        F8 h0 = gather_h8(hbuf, s0, l16);
        s += x0;
#pragma unroll
        for (int i = 0; i < 8; i++) a[i] += x0 * h0.v[i];
    }
}

// Two relations interleaved (order within each relation preserved).
__device__ __forceinline__ void agg_rel2(
    const int* __restrict__ srcs,
    int st1, int d1, const float* __restrict__ L1s, float ad1, const __half* __restrict__ hb1,
    int st2, int d2, const float* __restrict__ L2s, float ad2, const __half* __restrict__ hb2,
    int l16, int h, float* a1, float& s1, float* a2, float& s2) {
    int j1 = 0, j2 = 0;
    while (j1 + 2 <= d1 && j2 + 2 <= d2) {
        int p0 = srcs[st1 + j1], p1 = srcs[st1 + j1 + 1];
        int q0 = srcs[st2 + j2], q1 = srcs[st2 + j2 + 1];
        float lp0 = L1s[(size_t)p0 * 16 + h], lp1 = L1s[(size_t)p1 * 16 + h];
        float lq0 = L2s[(size_t)q0 * 16 + h], lq1 = L2s[(size_t)q1 * 16 + h];
        F8 hp0 = gather_h8(hb1, p0, l16);
        F8 hp1 = gather_h8(hb1, p1, l16);
        F8 hq0 = gather_h8(hb2, q0, l16);
        F8 hq1 = gather_h8(hb2, q1, l16);
        float x0 = __expf(lrelu02(lp0 + ad1));
        float x1 = __expf(lrelu02(lp1 + ad1));
        float y0 = __expf(lrelu02(lq0 + ad2));
        float y1 = __expf(lrelu02(lq1 + ad2));
        s1 += x0 + x1;
        s2 += y0 + y1;
#pragma unroll
        for (int i = 0; i < 8; i++) {
            a1[i] += x0 * hp0.v[i] + x1 * hp1.v[i];
            a2[i] += y0 * hq0.v[i] + y1 * hq1.v[i];
        }
        j1 += 2;
        j2 += 2;
    }
    agg_rel(srcs, st1 + j1, d1 - j1, L1s, ad1, hb1, l16, h, a1, s1);
    agg_rel(srcs, st2 + j2, d2 - j2, L2s, ad2, hb2, l16, h, a2, s2);
}

__device__ __forceinline__ void store_h8(__half* __restrict__ out, int n, int l16,
                                         const float* o) {
    uint4 u;
    uint32_t* p = &u.x;
#pragma unroll
    for (int i = 0; i < 4; i++) {
        __half2 h2 = __floats2half2_rn(o[2 * i], o[2 * i + 1]);
        p[i] = *reinterpret_cast<uint32_t*>(&h2);
    }
    reinterpret_cast<uint4*>(out + (size_t)n * HID)[l16] = u;
}

// Merged layer-0 aggregation: paper (2 relations) + author (1 relation).
__global__ void agg_l0_k(
    const int* __restrict__ srcs, const int* __restrict__ offs, const int* __restrict__ degs,
    const float* __restrict__ LP1, const __half* __restrict__ HP0,
    const float* __restrict__ LA,  const __half* __restrict__ HA1,
    const float* __restrict__ LP2, const __half* __restrict__ HP2,
    const float* __restrict__ BB, __half* __restrict__ XPB, __half* __restrict__ XAB) {
    const int gid  = blockIdx.x * blockDim.x + threadIdx.x;
    const int lane = threadIdx.x & 31;
    const int l16  = lane & 15;
    const int n    = ((gid >> 5) << 1) + (lane >> 4);
    if (n >= NPAPER + NAUTHOR) return;
    const int h = l16 >> 2;

    if (n < NPAPER) {
        float a1[8] = {0, 0, 0, 0, 0, 0, 0, 0};
        float a2[8] = {0, 0, 0, 0, 0, 0, 0, 0};
        float s1 = 0.f, s2 = 0.f;
        agg_rel2(srcs,
                 offs[n], degs[n], LP1, LP1[(size_t)n * 16 + 4 + h], HP0,
                 offs[NPAPER + n], degs[NPAPER + n], LA, LP1[(size_t)n * 16 + 8 + h], HA1,
                 l16, h, a1, s1, a2, s2);
        float i1 = 1.f / (s1 + 1e-16f);
        float i2 = 1.f / (s2 + 1e-16f);
        float4 ba_ = reinterpret_cast<const float4*>(BB)[l16 * 2];
        float4 bb_ = reinterpret_cast<const float4*>(BB)[l16 * 2 + 1];
        float4 ca_ = reinterpret_cast<const float4*>(BB + 128)[l16 * 2];
        float4 cb_ = reinterpret_cast<const float4*>(BB + 128)[l16 * 2 + 1];
        float bsum[8] = {ba_.x + ca_.x, ba_.y + ca_.y, ba_.z + ca_.z, ba_.w + ca_.w,
                         bb_.x + cb_.x, bb_.y + cb_.y, bb_.z + cb_.z, bb_.w + cb_.w};
        float o[8];
#pragma unroll
        for (int i = 0; i < 8; i++) {
            float v = a1[i] * i1 + a2[i] * i2 + bsum[i];
            o[i] = (v < 0.f) ? 0.01f * v : v;
        }
        store_h8(XPB, n, l16, o);
    } else {
        const int m = n - NPAPER;
        float a1[8] = {0, 0, 0, 0, 0, 0, 0, 0};
        float s1 = 0.f;
        agg_rel(srcs, offs[2 * NPAPER + m], degs[2 * NPAPER + m], LP2,
                LA[(size_t)m * 16 + 4 + h], HP2, l16, h, a1, s1);
        float i1 = 1.f / (s1 + 1e-16f);
        float4 ba_ = reinterpret_cast<const float4*>(BB + 256)[l16 * 2];
        float4 bb_ = reinterpret_cast<const float4*>(BB + 256)[l16 * 2 + 1];
        float bs[8] = {ba_.x, ba_.y, ba_.z, ba_.w, bb_.x, bb_.y, bb_.z, bb_.w};
        float o[8];
#pragma unroll
        for (int i = 0; i < 8; i++) {
            float v = a1[i] * i1 + bs[i];
            o[i] = (v < 0.f) ? 0.01f * v : v;
        }
        store_h8(XAB, m, l16, o);
    }
}

// Layer-1 paper aggregation (no activation).
__global__ void agg_paper_k(
    const int* __restrict__ srcs, const int* __restrict__ offs, const int* __restrict__ degs,
    const float* __restrict__ LP1, const __half* __restrict__ h1,
    const float* __restrict__ LA,  const __half* __restrict__ h2,
    const float* __restrict__ bb, __half* __restrict__ out) {
    const int gid  = blockIdx.x * blockDim.x + threadIdx.x;
    const int lane = threadIdx.x & 31;
    const int l16  = lane & 15;
    const int n    = ((gid >> 5) << 1) + (lane >> 4);
    if (n >= NPAPER) return;
    const int h = l16 >> 2;

    float a1[8] = {0, 0, 0, 0, 0, 0, 0, 0};
    float a2[8] = {0, 0, 0, 0, 0, 0, 0, 0};
    float s1 = 0.f, s2 = 0.f;
    agg_rel2(srcs,
             offs[n], degs[n], LP1, LP1[(size_t)n * 16 + 4 + h], h1,
             offs[NPAPER + n], degs[NPAPER + n], LA, LP1[(size_t)n * 16 + 8 + h], h2,
             l16, h, a1, s1, a2, s2);

    float i1 = 1.f / (s1 + 1e-16f);
    float i2 = 1.f / (s2 + 1e-16f);
    float4 bv1a = reinterpret_cast<const float4*>(bb)[l16 * 2];
    float4 bv1b = reinterpret_cast<const float4*>(bb)[l16 * 2 + 1];
    float4 bv2a = reinterpret_cast<const float4*>(bb + 128)[l16 * 2];
    float4 bv2b = reinterpret_cast<const float4*>(bb + 128)[l16 * 2 + 1];
    float bsum[8] = {bv1a.x + bv2a.x, bv1a.y + bv2a.y, bv1a.z + bv2a.z, bv1a.w + bv2a.w,
                     bv1b.x + bv2b.x, bv1b.y + bv2b.y, bv1b.z + bv2b.z, bv1b.w + bv2b.w};
    float o[8];
#pragma unroll
    for (int i = 0; i < 8; i++)
        o[i] = a1[i] * i1 + a2[i] * i2 + bsum[i];
    store_h8(out, n, l16, o);
}

// ---------------------------------------------------------------------------
// Host orchestration
// ---------------------------------------------------------------------------
static inline int gemm_smem(int N, int ach) {
    return (ach * 128 * 136 + 128 * (N + 8)) * 2;
}

extern "C" void kernel_launch(void* const* d_in, const int* in_sizes, int n_in,
                              void* d_out, int out_size) {
    const float* x_paper  = (const float*)d_in[0];
    const float* x_author = (const float*)d_in[1];
    const float* Wp   = (const float*)d_in[2];
    const float* bp   = (const float*)d_in[3];
    const float* Wa   = (const float*)d_in[4];
    const float* ba   = (const float*)d_in[5];
    const float* W0   = (const float*)d_in[6];
    const float* as0  = (const float*)d_in[7];
    const float* ad0  = (const float*)d_in[8];
    const float* b0   = (const float*)d_in[9];
    const float* W1   = (const float*)d_in[10];
    const float* as1  = (const float*)d_in[11];
    const float* ad1  = (const float*)d_in[12];
    const float* b1   = (const float*)d_in[13];
    const float* Wlin = (const float*)d_in[14];
    const float* blin = (const float*)d_in[15];
    const int* src_c  = (const int*)d_in[16];
    const int* dst_c  = (const int*)d_in[17];
    const int* src_w  = (const int*)d_in[18];
    const int* dst_w  = (const int*)d_in[19];
    const int* src_b  = (const int*)d_in[20];
    const int* dst_b  = (const int*)d_in[21];

    float* S = nullptr;
    cudaGetSymbolAddress((void**)&S, g_scratch);
    __half* Hh = nullptr;
    cudaGetSymbolAddress((void**)&Hh, g_hscratch);
    int* I = nullptr;
    cudaGetSymbolAddress((void**)&I, g_iscratch);
    void* FL = nullptr;
    cudaGetSymbolAddress(&FL, g_flags);

    float*  LP1 = S + O_LP1;
    float*  LP2 = S + O_LP2;
    float*  LA  = S + O_LA;
    float*  VF  = S + O_VF;
    float*  BB  = S + O_BB;
    __half* XPA = Hh + H_XPA;
    __half* XPB = Hh + H_XPB;
    __half* XAB = Hh + H_XAB;
    __half* HP0 = Hh + H_HP0;
    __half* HP2 = Hh + H_HP2;
    __half* HA1 = Hh + H_HA1;
    __half* HW1 = Hh + H_W1;
    __half* HWL = Hh + H_WLIN;
    __half* CWP0 = Hh + H_CWP0;
    __half* CWP2 = Hh + H_CWP2;
    __half* CWA  = Hh + H_CWA;
    __half* CV0  = Hh + H_CV0;
    __half* CV2  = Hh + H_CV2;
    __half* CVA  = Hh + H_CVA;
    __half* V16  = Hh + H_V16;

    int* DEGS = I + I_DEGS;
    int* OFFS = I + I_OFFS;
    int* CURS = I + I_CURS;
    int* SRCS = I + I_SRCS;

    const int smDual = gemm_smem(144, 2);
    const int sm144  = gemm_smem(144, 1);
    const int sm64   = gemm_smem(64, 1);
    cudaFuncSetAttribute(mma_gemm<144, 2, true,  true,  false, true,  false>, cudaFuncAttributeMaxDynamicSharedMemorySize, smDual);
    cudaFuncSetAttribute(mma_gemm<144, 1, true,  true,  false, false, false>, cudaFuncAttributeMaxDynamicSharedMemorySize, sm144);
    cudaFuncSetAttribute(mma_gemm<144, 1, true,  true,  true,  false, true >, cudaFuncAttributeMaxDynamicSharedMemorySize, sm144);
    cudaFuncSetAttribute(mma_gemm<64,  1, false, false, true,  false, false>, cudaFuncAttributeMaxDynamicSharedMemorySize, sm64);

    const int TP = (NPAPER + 127) / 128;
    const int TA = (NAUTHOR + 127) / 128;

    // ---- prep + merged CSR build ----
    prep_v_k<<<40, 256>>>(W0, as0, ad0, W1, as1, ad1, VF);
    prep_cw_k<<<602, 256>>>(Wp, Wa, W0, bp, ba, b0, VF, W1, Wlin,
                            CWP0, CWP2, CWA, CV0, CV2, CVA, V16, BB, HW1, HWL);
    cudaMemsetAsync(DEGS, 0, (size_t)NTOT * sizeof(int));
    cudaMemsetAsync(FL, 0, 256 * sizeof(unsigned long long));
    hist3_k<<<(ETOT + 255) / 256, 256>>>(dst_c, dst_w, dst_b, DEGS);
    scan_k<<<(NTOT + 2047) / 2048, 256>>>(DEGS, OFFS, CURS, NTOT);
    scatter3_k<<<(ETOT + 255) / 256, 256>>>(src_c, dst_c, src_w, dst_w, src_b, dst_b,
                                            CURS, SRCS);

    // ---- layer 0 (projection folded): A = raw fp32 inputs ----
    mma_gemm<144, 2, true, true, false, true, false><<<TP, 256, smDual>>>(
        x_paper, CWP0, CV0, HP0, LP1, CWP2, CV2, HP2, LP2, nullptr, NPAPER,
        nullptr, 0, 0);
    mma_gemm<144, 1, true, true, false, false, false><<<TA, 256, sm144>>>(
        x_author, CWA, CVA, HA1, LA,
        nullptr, nullptr, nullptr, nullptr, nullptr, NAUTHOR, nullptr, 0, 0);

    agg_l0_k<<<((NPAPER + NAUTHOR) * 16 + 255) / 256, 256>>>(
        SRCS, OFFS, DEGS, LP1, HP0, LA, HA1, LP2, HP2, BB, XPB, XAB);

    // ---- layer 1: paper + author GEMMs paired in one launch ----
    mma_gemm<144, 1, true, true, true, false, true><<<TP + TA, 256, sm144>>>(
        XPB, HW1 + 0 * HID * HID, V16 + 0 * 2048, HP0, LP1,
        HW1 + 1 * HID * HID, V16 + 1 * 2048, HA1, LA,
        nullptr, NPAPER, XAB, NAUTHOR, TP);

    agg_paper_k<<<(NPAPER * 16 + 255) / 256, 256>>>(
        SRCS, OFFS, DEGS, LP1, HP0, LA, HA1, b1, XPA);

    // ---- classifier: [200000,128] fp16 @ [128,64] fp16 + blin -> fp32 out ----
    mma_gemm<64, 1, false, false, true, false, false><<<TP, 256, sm64>>>(
        XPA, HWL, nullptr, d_out, nullptr,
        nullptr, nullptr, nullptr, nullptr, blin, NPAPER, nullptr, 0, 0);
}